// round 15
// baseline (speedup 1.0000x reference)
#include <cuda_runtime.h>
#include <cstdint>

#define NU 8192
#define NC 8192
#define NK 8192
#define D  32

// ---------------- scratch ----------------
__device__ float4 g_Bt[3 * 256 * 512];       // fragment-order B tiles (bh0,bh1,bl0,bl1), 8KB per (mat,ktile)
__device__ float g_part[4 * 3 * 8192 * 32];  // k-split(4) partials: plane = ksp*3+mat
__device__ float g_dinv_uu[NU];
__device__ float g_dinv_cc[NC];
__device__ float g_du[NU];
__device__ float g_colpart[512 * NC];        // 16 MB: per-block colsum partials (16 rows/block)
__device__ float g_colpart2[8 * NC];
__device__ float g_W2[D * D];

// ---------------- helpers ----------------
__device__ __forceinline__ uint32_t smem_u32(const void* p) {
    uint32_t a;
    asm("{ .reg .u64 t; cvta.to.shared.u64 t, %1; cvt.u32.u64 %0, t; }" : "=r"(a) : "l"(p));
    return a;
}
__device__ __forceinline__ void cp16(uint32_t dst, const void* src) {
    asm volatile("cp.async.cg.shared.global [%0], [%1], 16;" :: "r"(dst), "l"(src));
}
#define CP_COMMIT() asm volatile("cp.async.commit_group;" ::: "memory")
#define CP_WAIT1()  asm volatile("cp.async.wait_group 1;" ::: "memory")

__device__ __forceinline__ uint32_t tf32_rna(float x) {
    uint32_t r;
    asm("cvt.rna.tf32.f32 %0, %1;" : "=r"(r) : "f"(x));
    return r;
}
__device__ __forceinline__ float uif(uint32_t x) { return __uint_as_float(x); }

__device__ __forceinline__ void mma8(float* c, uint32_t a0, uint32_t a1,
                                     uint32_t a2, uint32_t a3,
                                     uint32_t b0, uint32_t b1) {
    asm volatile(
        "mma.sync.aligned.m16n8k8.row.col.f32.tf32.tf32.f32 "
        "{%0,%1,%2,%3}, {%4,%5,%6,%7}, {%8,%9}, {%0,%1,%2,%3};"
        : "+f"(c[0]), "+f"(c[1]), "+f"(c[2]), "+f"(c[3])
        : "r"(a0), "r"(a1), "r"(a2), "r"(a3), "r"(b0), "r"(b1));
}

__device__ __forceinline__ void ldsm4(uint32_t& r0, uint32_t& r1, uint32_t& r2,
                                      uint32_t& r3, uint32_t addr) {
    asm volatile("ldmatrix.sync.aligned.m8n8.x4.shared.b16 {%0,%1,%2,%3}, [%4];"
        : "=r"(r0), "=r"(r1), "=r"(r2), "=r"(r3) : "r"(addr));
}

// ---------------- fused pass-1 (heavy uc blocks scheduled FIRST) ----------------
// blocks [0,512):     adj_uc 16 rows/block: rowsums -> g_du, colsum partials -> g_colpart
// blocks [512,1536):  adj_uu rowsums (warp-per-row) -> g_dinv_uu
// blocks [1536,2560): adj_cc rowsums -> g_dinv_cc
__global__ void k_sums(const float* __restrict__ adj_uu,
                       const float* __restrict__ adj_cc,
                       const float* __restrict__ adj_uc) {
    int b = blockIdx.x;
    int tid = threadIdx.x;
    int w = tid >> 5, lane = tid & 31;

    if (b >= 512) {
        int bb = b - 512;
        const float* A = (bb < 1024) ? adj_uu : adj_cc;
        float* out = (bb < 1024) ? g_dinv_uu : g_dinv_cc;
        int row = ((bb < 1024) ? bb : (bb - 1024)) * 8 + w;
        const float4* p = (const float4*)(A + (size_t)row * NK) + lane;
        float s0 = 0.f, s1 = 0.f, s2 = 0.f, s3 = 0.f;
#pragma unroll 8
        for (int i = 0; i < 64; i++) {
            float4 v = p[(size_t)i * 32];
            s0 += v.x; s1 += v.y; s2 += v.z; s3 += v.w;
        }
        float s = (s0 + s1) + (s2 + s3);
#pragma unroll
        for (int o = 16; o; o >>= 1) s += __shfl_xor_sync(0xffffffffu, s, o);
        if (lane == 0) out[row] = rsqrtf(1.0f + s);
    } else {
        int ub = b;                   // 0..511
        int m0 = ub * 16;
        __shared__ float sm[16 * 8];  // [row][warp] partial rowsums
        float4 colacc[8];
#pragma unroll
        for (int i = 0; i < 8; i++) colacc[i] = make_float4(0.f, 0.f, 0.f, 0.f);

#pragma unroll 1
        for (int r = 0; r < 16; r++) {
            const float4* p = (const float4*)(adj_uc + (size_t)(m0 + r) * NK);
            float rs = 0.f;
#pragma unroll
            for (int i = 0; i < 8; i++) {
                float4 v = p[tid + i * 256];
                colacc[i].x += v.x; colacc[i].y += v.y;
                colacc[i].z += v.z; colacc[i].w += v.w;
                rs += (v.x + v.y) + (v.z + v.w);
            }
#pragma unroll
            for (int o = 16; o; o >>= 1) rs += __shfl_xor_sync(0xffffffffu, rs, o);
            if (lane == 0) sm[r * 8 + w] = rs;
        }
        __syncthreads();
        if (tid < 16) {
            float t = 0.f;
#pragma unroll
            for (int i = 0; i < 8; i++) t += sm[tid * 8 + i];
            g_du[m0 + tid] = rsqrtf(t);  // no +1 in gcn_c
        }
        float4* cp = (float4*)(g_colpart + (size_t)ub * NC);
#pragma unroll
        for (int i = 0; i < 8; i++) cp[tid + i * 256] = colacc[i];
    }
}

// ---------------- colsum stage-1 reduce (512 -> 8 planes) + W2 in block 255 ----------------
__global__ void k_dc1(const float* __restrict__ proj_u,
                      const float* __restrict__ weight_c) {
    int rc = blockIdx.x >> 5;  // 0..7, 64 planes each
    int c = (blockIdx.x & 31) * 256 + threadIdx.x;
    float a0 = 0.f, a1 = 0.f, a2 = 0.f, a3 = 0.f;
#pragma unroll 4
    for (int r = rc * 64; r < rc * 64 + 64; r += 4) {
        a0 += g_colpart[(size_t)(r + 0) * NC + c];
        a1 += g_colpart[(size_t)(r + 1) * NC + c];
        a2 += g_colpart[(size_t)(r + 2) * NC + c];
        a3 += g_colpart[(size_t)(r + 3) * NC + c];
    }
    g_colpart2[(size_t)rc * NC + c] = (a0 + a1) + (a2 + a3);

    if (blockIdx.x == 255) {  // W2 = proj_u @ weight_c (independent of colpart)
        int tid = threadIdx.x;
#pragma unroll
        for (int q = 0; q < 4; q++) {
            int e = tid * 4 + q;
            int i = e >> 5, j = e & 31;
            float t = 0.f;
#pragma unroll
            for (int k = 0; k < 32; k++) t += proj_u[i * 32 + k] * weight_c[k * 32 + j];
            g_W2[e] = t;
        }
    }
}

// ---------------- build B tiles in mma-fragment order (hi/lo split) ----------------
// mat-2 blocks derive their 32 dc values from g_colpart2 inline.
__global__ void k_build_b(const float* __restrict__ X_U,
                          const float* __restrict__ X_C,
                          const float* __restrict__ weight_s) {
    __shared__ __align__(16) float Ws[1024];
    __shared__ float Xs[1024];
    __shared__ float sup[32 * 33];
    __shared__ float tmp[256];
    __shared__ float dcs[32];
    int mat = blockIdx.y;
    int ktile = blockIdx.x;
    int tid = threadIdx.x;  // 256

    const float* W = (mat == 2) ? g_W2 : weight_s;
#pragma unroll
    for (int e = tid; e < 1024; e += 256) Ws[e] = W[e];
    const float* X = (mat == 1) ? X_C : X_U;
#pragma unroll
    for (int e = tid; e < 1024; e += 256) Xs[e] = X[(size_t)ktile * 1024 + e];
    if (mat == 2) {
        int kk = tid & 31, pp = tid >> 5;  // coalesced
        tmp[tid] = g_colpart2[(size_t)pp * NC + ktile * 32 + kk];
    }
    __syncthreads();
    if (mat == 2 && tid < 32) {
        float t = 0.f;
#pragma unroll
        for (int i = 0; i < 8; i++) t += tmp[i * 32 + tid];
        dcs[tid] = rsqrtf(t);
    }
    __syncthreads();

    {
        int k = tid >> 3;
        int nq = (tid & 7) * 4;
        float scale;
        int gk = ktile * 32 + k;
        if (mat == 0)      scale = g_dinv_uu[gk];
        else if (mat == 1) scale = g_dinv_cc[gk];
        else               scale = dcs[k];
        float s0 = 0.f, s1 = 0.f, s2 = 0.f, s3 = 0.f;
#pragma unroll
        for (int j = 0; j < 32; j++) {
            float xj = Xs[k * 32 + j];
            float4 wv = *(const float4*)(Ws + j * 32 + nq);
            s0 = fmaf(xj, wv.x, s0);
            s1 = fmaf(xj, wv.y, s1);
            s2 = fmaf(xj, wv.z, s2);
            s3 = fmaf(xj, wv.w, s3);
        }
        sup[k * 33 + nq + 0] = scale * s0;
        sup[k * 33 + nq + 1] = scale * s1;
        sup[k * 33 + nq + 2] = scale * s2;
        sup[k * 33 + nq + 3] = scale * s3;
    }
    __syncthreads();

    float4* dst = g_Bt + ((size_t)mat * 256 + ktile) * 512;
#pragma unroll
    for (int it = 0; it < 2; it++) {
        int e = tid + it * 256;
        int lane = e & 31, nt = (e >> 5) & 3, ks = e >> 7;
        int la = lane & 3, gr = lane >> 2;
        int k0 = ks * 8 + la, n = nt * 8 + gr;
        float b0 = sup[k0 * 33 + n];
        float b1 = sup[(k0 + 4) * 33 + n];
        float h0 = uif(tf32_rna(b0));
        float h1 = uif(tf32_rna(b1));
        dst[e] = make_float4(h0, h1, b0 - h0, b1 - h1);
    }
}

// ---------------- tensor-core 2-term TF32 SpMM with ldmatrix A path, K-split x4 ----------------
// grid 768: mat = x>>8, mb = (x&255)>>2, ksp = x&3. 128 thr, warp = m32. 3 CTAs/SM by smem.
// Stage (24KB) = [A 128x32 f32, 16B-unit XOR swizzle unit16=r*8+(q^(r&7)) | B 8KB fragment order].
// 3 stages, one cp.async group per chunk, wait_group 1 => 2 chunks in flight.
#define NCH4 64
#define STAGE 24576
__global__ void __launch_bounds__(128) k_tc(
    const float* __restrict__ adj_uu, const float* __restrict__ adj_cc,
    const float* __restrict__ adj_uc) {
    extern __shared__ char smem[];
    uint32_t sb = smem_u32(smem);

    int tid = threadIdx.x, wid = tid >> 5, lane = tid & 31;
    int mat = blockIdx.x >> 8;
    int rem = blockIdx.x & 255;
    int mb = rem >> 2, ksp = rem & 3;
    int m0 = mb * 128;
    int kbase = ksp * NCH4;

    const float* A = (mat == 0) ? adj_uu : (mat == 1) ? adj_cc : adj_uc;
    const float4* Bg = g_Bt + ((size_t)mat * 256 + kbase) * 512;
    const float* Ag = A + (size_t)m0 * NK + (size_t)kbase * 32;

    // cp.async map for A: e = i*128 + tid -> r = e>>3 (0..127), q = e&7 (16B block)
    const float* asrc[8];
    uint32_t adst[8];
#pragma unroll
    for (int i = 0; i < 8; i++) {
        int e = i * 128 + tid;
        int r = e >> 3, q = e & 7;
        asrc[i] = Ag + (size_t)r * NK + q * 4;
        adst[i] = (uint32_t)((r * 8 + (q ^ (r & 7))) * 16);
    }
    uint32_t bdst = (uint32_t)(16384 + tid * 16);
    const char* bsrc = (const char*)Bg + tid * 16;

    // ldmatrix per-thread offsets for (mt, ks): matrix id m = lane>>3
    uint32_t offA[8];
    {
        int m = lane >> 3;
#pragma unroll
        for (int mt = 0; mt < 2; mt++) {
#pragma unroll
            for (int ks = 0; ks < 4; ks++) {
                int r = wid * 32 + mt * 16 + (m & 1) * 8 + (lane & 7);
                int q = ks * 2 + (m >> 1);
                offA[mt * 4 + ks] = (uint32_t)((r * 8 + (q ^ (r & 7))) * 16);
            }
        }
    }

    // prologue: issue chunks 0, 1
#pragma unroll
    for (int pc = 0; pc < 2; pc++) {
        uint32_t sa = sb + (uint32_t)pc * STAGE;
#pragma unroll
        for (int i = 0; i < 8; i++) cp16(sa + adst[i], asrc[i] + pc * 32);
#pragma unroll
        for (int j = 0; j < 4; j++)
            cp16(sa + bdst + (uint32_t)j * 2048, bsrc + (size_t)pc * 8192 + j * 2048);
        CP_COMMIT();
    }

    float acc[32];
#pragma unroll
    for (int i = 0; i < 32; i++) acc[i] = 0.f;

    int s = 0, s2 = 2;  // stage of chunk t, stage of chunk t+2
    for (int t = 0; t < NCH4; t++) {
        CP_WAIT1();
        __syncthreads();

        // issue chunk t+2 into the stage freed at iter t-1
        if (t + 2 < NCH4) {
            uint32_t sa = sb + (uint32_t)s2 * STAGE;
#pragma unroll
            for (int i = 0; i < 8; i++) cp16(sa + adst[i], asrc[i] + (t + 2) * 32);
#pragma unroll
            for (int j = 0; j < 4; j++)
                cp16(sa + bdst + (uint32_t)j * 2048, bsrc + (size_t)(t + 2) * 8192 + j * 2048);
        }
        CP_COMMIT();  // always commit so wait_group counting holds through the tail

        uint32_t abase = sb + (uint32_t)s * STAGE;
        const char* stc = smem + s * STAGE + 16384;
#pragma unroll
        for (int ks = 0; ks < 4; ks++) {
            uint32_t ah[8];
#pragma unroll
            for (int mt = 0; mt < 2; mt++) {
                uint32_t r0, r1, r2, r3;
                ldsm4(r0, r1, r2, r3, abase + offA[mt * 4 + ks]);
                ah[mt * 4 + 0] = tf32_rna(uif(r0));
                ah[mt * 4 + 1] = tf32_rna(uif(r1));
                ah[mt * 4 + 2] = tf32_rna(uif(r2));
                ah[mt * 4 + 3] = tf32_rna(uif(r3));
            }
#pragma unroll
            for (int nt = 0; nt < 4; nt++) {
                float4 b = *(const float4*)(stc + ((ks * 4 + nt) * 32 + lane) * 16);
                uint32_t bh0 = __float_as_uint(b.x);
                uint32_t bh1 = __float_as_uint(b.y);
                uint32_t bl0 = __float_as_uint(b.z);
                uint32_t bl1 = __float_as_uint(b.w);
#pragma unroll
                for (int mt = 0; mt < 2; mt++) {
                    float* c = acc + mt * 16 + nt * 4;
                    mma8(c, ah[mt * 4 + 0], ah[mt * 4 + 1], ah[mt * 4 + 2], ah[mt * 4 + 3], bh0, bh1);
                    mma8(c, ah[mt * 4 + 0], ah[mt * 4 + 1], ah[mt * 4 + 2], ah[mt * 4 + 3], bl0, bl1);
                }
            }
        }
        if (++s == 3) s = 0;
        if (++s2 == 3) s2 = 0;
    }

    // partial (unscaled) store: plane = ksp*3 + mat
    float* P = g_part + ((size_t)ksp * 3 + mat) * (8192 * 32);
    int rA = m0 + wid * 32 + (lane >> 2);
#pragma unroll
    for (int mt = 0; mt < 2; mt++) {
        int row0 = rA + mt * 16;
        int row1 = row0 + 8;
#pragma unroll
        for (int nt = 0; nt < 4; nt++) {
            float* c = acc + mt * 16 + nt * 4;
            int col = nt * 8 + 2 * (lane & 3);
            *(float2*)(P + (size_t)row0 * 32 + col) = make_float2(c[0], c[1]);
            *(float2*)(P + (size_t)row1 * 32 + col) = make_float2(c[2], c[3]);
        }
    }
}

// ---------------- fused: combine 4-way partials + row scale + attention + outputs ----------------
__global__ void k_fin(const float* __restrict__ X_C,
                      const float* __restrict__ W_lin,
                      const float* __restrict__ a_vec,
                      float* __restrict__ out) {
    __shared__ float Ws[64 * 32];
    __shared__ float av[32];
    int tid = threadIdx.x;  // 256
    for (int i = tid; i < 2048; i += 256) Ws[i] = W_lin[i];
    if (tid < 32) av[tid] = a_vec[tid];
    __syncthreads();

    int lane = tid & 31;
    int row = blockIdx.x * 8 + (tid >> 5);
    size_t idx = (size_t)row * 32 + lane;

    const size_t PL = 262144;
    float pu = (g_part[idx] + g_part[3 * PL + idx]) +
               (g_part[6 * PL + idx] + g_part[9 * PL + idx]);
    out[idx] = g_dinv_uu[row] * pu;

    float c1v = g_dinv_cc[row] * ((g_part[1 * PL + idx] + g_part[4 * PL + idx]) +
                                  (g_part[7 * PL + idx] + g_part[10 * PL + idx]));
    float c2v = g_du[row] * ((g_part[2 * PL + idx] + g_part[5 * PL + idx]) +
                             (g_part[8 * PL + idx] + g_part[11 * PL + idx]));
    float xcv = X_C[idx];

    float h1a = 0.f, h1b = 0.f, h2a = 0.f, h2b = 0.f;
#pragma unroll
    for (int k = 0; k < 32; k += 2) {
        float u1 = __shfl_sync(0xffffffffu, c1v, k);
        float u2 = __shfl_sync(0xffffffffu, c2v, k);
        float u1o = __shfl_sync(0xffffffffu, c1v, k + 1);
        float u2o = __shfl_sync(0xffffffffu, c2v, k + 1);
        float w0 = Ws[k * 32 + lane];
        float w0o = Ws[(k + 1) * 32 + lane];
        h1a = fmaf(u1, w0, h1a);
        h2a = fmaf(u2, w0, h2a);
        h1b = fmaf(u1o, w0o, h1b);
        h2b = fmaf(u2o, w0o, h2b);
    }
#pragma unroll
    for (int k = 0; k < 32; k += 2) {
        float ux = __shfl_sync(0xffffffffu, xcv, k);
        float uxo = __shfl_sync(0xffffffffu, xcv, k + 1);
        float w1 = Ws[(32 + k) * 32 + lane];
        float w1o = Ws[(33 + k) * 32 + lane];
        h1a = fmaf(ux, w1, h1a);
        h2a = fmaf(ux, w1, h2a);
        h1b = fmaf(uxo, w1o, h1b);
        h2b = fmaf(uxo, w1o, h2b);
    }
    float h1 = h1a + h1b, h2 = h2a + h2b;
    float t1 = fmaxf(h1, 0.f) * av[lane];
    float t2 = fmaxf(h2, 0.f) * av[lane];
#pragma unroll
    for (int o = 16; o; o >>= 1) {
        t1 += __shfl_xor_sync(0xffffffffu, t1, o);
        t2 += __shfl_xor_sync(0xffffffffu, t2, o);
    }
    float m = fmaxf(t1, t2);
    float e1 = expf(t1 - m), e2 = expf(t2 - m);
    float inv = 1.f / (e1 + e2);
    float yc = (e1 * inv) * c1v;
    float yu = (e2 * inv) * c2v;

    out[262144 + idx] = yc + yu;
    out[524288 + idx] = yc;
    out[786432 + idx] = yu;
}

// ---------------- launch ----------------
extern "C" void kernel_launch(void* const* d_in, const int* in_sizes, int n_in,
                              void* d_out, int out_size) {
    const float* X_U      = (const float*)d_in[0];
    const float* X_C      = (const float*)d_in[1];
    const float* adj_uu   = (const float*)d_in[2];
    const float* adj_uc   = (const float*)d_in[3];
    const float* adj_cc   = (const float*)d_in[4];
    const float* weight_s = (const float*)d_in[5];
    const float* proj_u   = (const float*)d_in[6];
    const float* weight_c = (const float*)d_in[8];
    const float* W_lin    = (const float*)d_in[9];
    const float* a_vec    = (const float*)d_in[10];
    float* out = (float*)d_out;

    cudaFuncSetAttribute(k_tc, cudaFuncAttributeMaxDynamicSharedMemorySize, 3 * STAGE);

    k_sums<<<2560, 256>>>(adj_uu, adj_cc, adj_uc);
    k_dc1<<<256, 256>>>(proj_u, weight_c);
    k_build_b<<<dim3(256, 3), 256>>>(X_U, X_C, weight_s);
    k_tc<<<768, 128, 3 * STAGE>>>(adj_uu, adj_cc, adj_uc);
    k_fin<<<1024, 256>>>(X_C, W_lin, a_vec, out);
}

// round 16
// speedup vs baseline: 1.0111x; 1.0111x over previous
#include <cuda_runtime.h>
#include <cstdint>

#define NU 8192
#define NC 8192
#define NK 8192
#define D  32

// ---------------- scratch ----------------
__device__ float4 g_Bt[3 * 256 * 512];       // fragment-order B tiles (bh0,bh1,bl0,bl1), 8KB per (mat,ktile)
__device__ float g_part[2 * 3 * 8192 * 32];  // k-split(2) partials: plane = ksp*3+mat
__device__ float g_dinv_uu[NU];
__device__ float g_dinv_cc[NC];
__device__ float g_du[NU];
__device__ float g_colpart[512 * NC];        // 16 MB: per-block colsum partials (16 rows/block)
__device__ float g_colpart2[8 * NC];
__device__ float g_W2[D * D];

// ---------------- helpers ----------------
__device__ __forceinline__ uint32_t smem_u32(const void* p) {
    uint32_t a;
    asm("{ .reg .u64 t; cvta.to.shared.u64 t, %1; cvt.u32.u64 %0, t; }" : "=r"(a) : "l"(p));
    return a;
}
__device__ __forceinline__ void cp16(uint32_t dst, const void* src) {
    asm volatile("cp.async.cg.shared.global [%0], [%1], 16;" :: "r"(dst), "l"(src));
}
#define CP_COMMIT() asm volatile("cp.async.commit_group;" ::: "memory")
#define CP_WAIT1()  asm volatile("cp.async.wait_group 1;" ::: "memory")

__device__ __forceinline__ uint32_t tf32_rna(float x) {
    uint32_t r;
    asm("cvt.rna.tf32.f32 %0, %1;" : "=r"(r) : "f"(x));
    return r;
}
__device__ __forceinline__ float uif(uint32_t x) { return __uint_as_float(x); }

__device__ __forceinline__ void mma8(float* c, uint32_t a0, uint32_t a1,
                                     uint32_t a2, uint32_t a3,
                                     uint32_t b0, uint32_t b1) {
    asm volatile(
        "mma.sync.aligned.m16n8k8.row.col.f32.tf32.tf32.f32 "
        "{%0,%1,%2,%3}, {%4,%5,%6,%7}, {%8,%9}, {%0,%1,%2,%3};"
        : "+f"(c[0]), "+f"(c[1]), "+f"(c[2]), "+f"(c[3])
        : "r"(a0), "r"(a1), "r"(a2), "r"(a3), "r"(b0), "r"(b1));
}

__device__ __forceinline__ void ldsm4(uint32_t& r0, uint32_t& r1, uint32_t& r2,
                                      uint32_t& r3, uint32_t addr) {
    asm volatile("ldmatrix.sync.aligned.m8n8.x4.shared.b16 {%0,%1,%2,%3}, [%4];"
        : "=r"(r0), "=r"(r1), "=r"(r2), "=r"(r3) : "r"(addr));
}

// ---------------- fused pass-1 (heavy uc blocks scheduled FIRST) ----------------
// blocks [0,512):     adj_uc 16 rows/block: rowsums -> g_du, colsum partials -> g_colpart
// blocks [512,1536):  adj_uu rowsums (warp-per-row) -> g_dinv_uu
// blocks [1536,2560): adj_cc rowsums -> g_dinv_cc
__global__ void k_sums(const float* __restrict__ adj_uu,
                       const float* __restrict__ adj_cc,
                       const float* __restrict__ adj_uc) {
    int b = blockIdx.x;
    int tid = threadIdx.x;
    int w = tid >> 5, lane = tid & 31;

    if (b >= 512) {
        int bb = b - 512;
        const float* A = (bb < 1024) ? adj_uu : adj_cc;
        float* out = (bb < 1024) ? g_dinv_uu : g_dinv_cc;
        int row = ((bb < 1024) ? bb : (bb - 1024)) * 8 + w;
        const float4* p = (const float4*)(A + (size_t)row * NK) + lane;
        float s0 = 0.f, s1 = 0.f, s2 = 0.f, s3 = 0.f;
#pragma unroll 8
        for (int i = 0; i < 64; i++) {
            float4 v = p[(size_t)i * 32];
            s0 += v.x; s1 += v.y; s2 += v.z; s3 += v.w;
        }
        float s = (s0 + s1) + (s2 + s3);
#pragma unroll
        for (int o = 16; o; o >>= 1) s += __shfl_xor_sync(0xffffffffu, s, o);
        if (lane == 0) out[row] = rsqrtf(1.0f + s);
    } else {
        int ub = b;                   // 0..511
        int m0 = ub * 16;
        __shared__ float sm[16 * 8];  // [row][warp] partial rowsums
        float4 colacc[8];
#pragma unroll
        for (int i = 0; i < 8; i++) colacc[i] = make_float4(0.f, 0.f, 0.f, 0.f);

#pragma unroll 1
        for (int r = 0; r < 16; r++) {
            const float4* p = (const float4*)(adj_uc + (size_t)(m0 + r) * NK);
            float rs = 0.f;
#pragma unroll
            for (int i = 0; i < 8; i++) {
                float4 v = p[tid + i * 256];
                colacc[i].x += v.x; colacc[i].y += v.y;
                colacc[i].z += v.z; colacc[i].w += v.w;
                rs += (v.x + v.y) + (v.z + v.w);
            }
#pragma unroll
            for (int o = 16; o; o >>= 1) rs += __shfl_xor_sync(0xffffffffu, rs, o);
            if (lane == 0) sm[r * 8 + w] = rs;
        }
        __syncthreads();
        if (tid < 16) {
            float t = 0.f;
#pragma unroll
            for (int i = 0; i < 8; i++) t += sm[tid * 8 + i];
            g_du[m0 + tid] = rsqrtf(t);  // no +1 in gcn_c
        }
        float4* cp = (float4*)(g_colpart + (size_t)ub * NC);
#pragma unroll
        for (int i = 0; i < 8; i++) cp[tid + i * 256] = colacc[i];
    }
}

// ---------------- colsum stage-1 reduce (512 -> 8 planes) + W2 in block 255 ----------------
__global__ void k_dc1(const float* __restrict__ proj_u,
                      const float* __restrict__ weight_c) {
    int rc = blockIdx.x >> 5;  // 0..7, 64 planes each
    int c = (blockIdx.x & 31) * 256 + threadIdx.x;
    float a0 = 0.f, a1 = 0.f, a2 = 0.f, a3 = 0.f;
#pragma unroll 4
    for (int r = rc * 64; r < rc * 64 + 64; r += 4) {
        a0 += g_colpart[(size_t)(r + 0) * NC + c];
        a1 += g_colpart[(size_t)(r + 1) * NC + c];
        a2 += g_colpart[(size_t)(r + 2) * NC + c];
        a3 += g_colpart[(size_t)(r + 3) * NC + c];
    }
    g_colpart2[(size_t)rc * NC + c] = (a0 + a1) + (a2 + a3);

    if (blockIdx.x == 255) {  // W2 = proj_u @ weight_c (independent of colpart)
        int tid = threadIdx.x;
#pragma unroll
        for (int q = 0; q < 4; q++) {
            int e = tid * 4 + q;
            int i = e >> 5, j = e & 31;
            float t = 0.f;
#pragma unroll
            for (int k = 0; k < 32; k++) t += proj_u[i * 32 + k] * weight_c[k * 32 + j];
            g_W2[e] = t;
        }
    }
}

// ---------------- build B tiles in mma-fragment order (hi/lo split) ----------------
// mat-2 blocks derive their 32 dc values from g_colpart2 inline (dc2 kernel eliminated).
__global__ void k_build_b(const float* __restrict__ X_U,
                          const float* __restrict__ X_C,
                          const float* __restrict__ weight_s) {
    __shared__ __align__(16) float Ws[1024];
    __shared__ float Xs[1024];
    __shared__ float sup[32 * 33];
    __shared__ float tmp[256];
    __shared__ float dcs[32];
    int mat = blockIdx.y;
    int ktile = blockIdx.x;
    int tid = threadIdx.x;  // 256

    const float* W = (mat == 2) ? g_W2 : weight_s;
#pragma unroll
    for (int e = tid; e < 1024; e += 256) Ws[e] = W[e];
    const float* X = (mat == 1) ? X_C : X_U;
#pragma unroll
    for (int e = tid; e < 1024; e += 256) Xs[e] = X[(size_t)ktile * 1024 + e];
    if (mat == 2) {
        int kk = tid & 31, pp = tid >> 5;  // coalesced: consecutive tid -> consecutive cols
        tmp[tid] = g_colpart2[(size_t)pp * NC + ktile * 32 + kk];
    }
    __syncthreads();
    if (mat == 2 && tid < 32) {
        float t = 0.f;
#pragma unroll
        for (int i = 0; i < 8; i++) t += tmp[i * 32 + tid];
        dcs[tid] = rsqrtf(t);
    }
    __syncthreads();

    {
        int k = tid >> 3;
        int nq = (tid & 7) * 4;
        float scale;
        int gk = ktile * 32 + k;
        if (mat == 0)      scale = g_dinv_uu[gk];
        else if (mat == 1) scale = g_dinv_cc[gk];
        else               scale = dcs[k];
        float s0 = 0.f, s1 = 0.f, s2 = 0.f, s3 = 0.f;
#pragma unroll
        for (int j = 0; j < 32; j++) {
            float xj = Xs[k * 32 + j];
            float4 wv = *(const float4*)(Ws + j * 32 + nq);
            s0 = fmaf(xj, wv.x, s0);
            s1 = fmaf(xj, wv.y, s1);
            s2 = fmaf(xj, wv.z, s2);
            s3 = fmaf(xj, wv.w, s3);
        }
        sup[k * 33 + nq + 0] = scale * s0;
        sup[k * 33 + nq + 1] = scale * s1;
        sup[k * 33 + nq + 2] = scale * s2;
        sup[k * 33 + nq + 3] = scale * s3;
    }
    __syncthreads();

    float4* dst = g_Bt + ((size_t)mat * 256 + ktile) * 512;
#pragma unroll
    for (int it = 0; it < 2; it++) {
        int e = tid + it * 256;
        int lane = e & 31, nt = (e >> 5) & 3, ks = e >> 7;
        int la = lane & 3, gr = lane >> 2;
        int k0 = ks * 8 + la, n = nt * 8 + gr;
        float b0 = sup[k0 * 33 + n];
        float b1 = sup[(k0 + 4) * 33 + n];
        float h0 = uif(tf32_rna(b0));
        float h1 = uif(tf32_rna(b1));
        dst[e] = make_float4(h0, h1, b0 - h0, b1 - h1);
    }
}

// ---------------- tensor-core 2-term TF32 SpMM with ldmatrix A path ----------------
// grid 384: mat = x>>7, mb = (x&127)>>1, ksp = x&1. 128 thr, warp = m32.
// Stage (24KB) = [A 128x32 f32, 16B-unit XOR swizzle unit16=r*8+(q^(r&7)) | B 8KB fragment order].
// 3 stages, one cp.async group per chunk, wait_group 1 => 2 chunks in flight.
#define NCH2 128
#define STAGE 24576
__global__ void __launch_bounds__(128) k_tc(
    const float* __restrict__ adj_uu, const float* __restrict__ adj_cc,
    const float* __restrict__ adj_uc) {
    extern __shared__ char smem[];
    uint32_t sb = smem_u32(smem);

    int tid = threadIdx.x, wid = tid >> 5, lane = tid & 31;
    int mat = blockIdx.x >> 7;
    int rem = blockIdx.x & 127;
    int mb = rem >> 1, ksp = rem & 1;
    int m0 = mb * 128;
    int kbase = ksp * NCH2;

    const float* A = (mat == 0) ? adj_uu : (mat == 1) ? adj_cc : adj_uc;
    const float4* Bg = g_Bt + ((size_t)mat * 256 + kbase) * 512;
    const float* Ag = A + (size_t)m0 * NK + (size_t)kbase * 32;

    // cp.async map for A: e = i*128 + tid -> r = e>>3 (0..127), q = e&7 (16B block)
    const float* asrc[8];
    uint32_t adst[8];
#pragma unroll
    for (int i = 0; i < 8; i++) {
        int e = i * 128 + tid;
        int r = e >> 3, q = e & 7;
        asrc[i] = Ag + (size_t)r * NK + q * 4;
        adst[i] = (uint32_t)((r * 8 + (q ^ (r & 7))) * 16);
    }
    uint32_t bdst = (uint32_t)(16384 + tid * 16);
    const char* bsrc = (const char*)Bg + tid * 16;

    // ldmatrix per-thread offsets for (mt, ks): matrix id m = lane>>3
    uint32_t offA[8];
    {
        int m = lane >> 3;
#pragma unroll
        for (int mt = 0; mt < 2; mt++) {
#pragma unroll
            for (int ks = 0; ks < 4; ks++) {
                int r = wid * 32 + mt * 16 + (m & 1) * 8 + (lane & 7);
                int q = ks * 2 + (m >> 1);
                offA[mt * 4 + ks] = (uint32_t)((r * 8 + (q ^ (r & 7))) * 16);
            }
        }
    }

    // prologue: issue chunks 0, 1
#pragma unroll
    for (int pc = 0; pc < 2; pc++) {
        uint32_t sa = sb + (uint32_t)pc * STAGE;
#pragma unroll
        for (int i = 0; i < 8; i++) cp16(sa + adst[i], asrc[i] + pc * 32);
#pragma unroll
        for (int j = 0; j < 4; j++)
            cp16(sa + bdst + (uint32_t)j * 2048, bsrc + (size_t)pc * 8192 + j * 2048);
        CP_COMMIT();
    }

    float acc[32];
#pragma unroll
    for (int i = 0; i < 32; i++) acc[i] = 0.f;

    int s = 0, s2 = 2;  // stage of chunk t, stage of chunk t+2
    for (int t = 0; t < NCH2; t++) {
        CP_WAIT1();
        __syncthreads();

        // issue chunk t+2 into the stage freed at iter t-1
        if (t + 2 < NCH2) {
            uint32_t sa = sb + (uint32_t)s2 * STAGE;
#pragma unroll
            for (int i = 0; i < 8; i++) cp16(sa + adst[i], asrc[i] + (t + 2) * 32);
#pragma unroll
            for (int j = 0; j < 4; j++)
                cp16(sa + bdst + (uint32_t)j * 2048, bsrc + (size_t)(t + 2) * 8192 + j * 2048);
        }
        CP_COMMIT();  // always commit so wait_group counting holds through the tail

        uint32_t abase = sb + (uint32_t)s * STAGE;
        const char* stc = smem + s * STAGE + 16384;
#pragma unroll
        for (int ks = 0; ks < 4; ks++) {
            uint32_t ah[8];
#pragma unroll
            for (int mt = 0; mt < 2; mt++) {
                uint32_t r0, r1, r2, r3;
                ldsm4(r0, r1, r2, r3, abase + offA[mt * 4 + ks]);
                ah[mt * 4 + 0] = tf32_rna(uif(r0));
                ah[mt * 4 + 1] = tf32_rna(uif(r1));
                ah[mt * 4 + 2] = tf32_rna(uif(r2));
                ah[mt * 4 + 3] = tf32_rna(uif(r3));
            }
#pragma unroll
            for (int nt = 0; nt < 4; nt++) {
                float4 b = *(const float4*)(stc + ((ks * 4 + nt) * 32 + lane) * 16);
                uint32_t bh0 = __float_as_uint(b.x);
                uint32_t bh1 = __float_as_uint(b.y);
                uint32_t bl0 = __float_as_uint(b.z);
                uint32_t bl1 = __float_as_uint(b.w);
#pragma unroll
                for (int mt = 0; mt < 2; mt++) {
                    float* c = acc + mt * 16 + nt * 4;
                    mma8(c, ah[mt * 4 + 0], ah[mt * 4 + 1], ah[mt * 4 + 2], ah[mt * 4 + 3], bh0, bh1);
                    mma8(c, ah[mt * 4 + 0], ah[mt * 4 + 1], ah[mt * 4 + 2], ah[mt * 4 + 3], bl0, bl1);
                }
            }
        }
        if (++s == 3) s = 0;
        if (++s2 == 3) s2 = 0;
    }

    // partial (unscaled) store: plane = ksp*3 + mat
    float* P = g_part + ((size_t)ksp * 3 + mat) * (8192 * 32);
    int rA = m0 + wid * 32 + (lane >> 2);
#pragma unroll
    for (int mt = 0; mt < 2; mt++) {
        int row0 = rA + mt * 16;
        int row1 = row0 + 8;
#pragma unroll
        for (int nt = 0; nt < 4; nt++) {
            float* c = acc + mt * 16 + nt * 4;
            int col = nt * 8 + 2 * (lane & 3);
            *(float2*)(P + (size_t)row0 * 32 + col) = make_float2(c[0], c[1]);
            *(float2*)(P + (size_t)row1 * 32 + col) = make_float2(c[2], c[3]);
        }
    }
}

// ---------------- fused: combine partials + row scale + attention + outputs ----------------
__global__ void k_fin(const float* __restrict__ X_C,
                      const float* __restrict__ W_lin,
                      const float* __restrict__ a_vec,
                      float* __restrict__ out) {
    __shared__ float Ws[64 * 32];
    __shared__ float av[32];
    int tid = threadIdx.x;  // 256
    for (int i = tid; i < 2048; i += 256) Ws[i] = W_lin[i];
    if (tid < 32) av[tid] = a_vec[tid];
    __syncthreads();

    int lane = tid & 31;
    int row = blockIdx.x * 8 + (tid >> 5);
    size_t idx = (size_t)row * 32 + lane;

    const size_t PL = 262144;
    float pu = g_part[idx] + g_part[3 * PL + idx];
    out[idx] = g_dinv_uu[row] * pu;

    float c1v = g_dinv_cc[row] * (g_part[1 * PL + idx] + g_part[4 * PL + idx]);
    float c2v = g_du[row] * (g_part[2 * PL + idx] + g_part[5 * PL + idx]);
    float xcv = X_C[idx];

    float h1a = 0.f, h1b = 0.f, h2a = 0.f, h2b = 0.f;
#pragma unroll
    for (int k = 0; k < 32; k += 2) {
        float u1 = __shfl_sync(0xffffffffu, c1v, k);
        float u2 = __shfl_sync(0xffffffffu, c2v, k);
        float u1o = __shfl_sync(0xffffffffu, c1v, k + 1);
        float u2o = __shfl_sync(0xffffffffu, c2v, k + 1);
        float w0 = Ws[k * 32 + lane];
        float w0o = Ws[(k + 1) * 32 + lane];
        h1a = fmaf(u1, w0, h1a);
        h2a = fmaf(u2, w0, h2a);
        h1b = fmaf(u1o, w0o, h1b);
        h2b = fmaf(u2o, w0o, h2b);
    }
#pragma unroll
    for (int k = 0; k < 32; k += 2) {
        float ux = __shfl_sync(0xffffffffu, xcv, k);
        float uxo = __shfl_sync(0xffffffffu, xcv, k + 1);
        float w1 = Ws[(32 + k) * 32 + lane];
        float w1o = Ws[(33 + k) * 32 + lane];
        h1a = fmaf(ux, w1, h1a);
        h2a = fmaf(ux, w1, h2a);
        h1b = fmaf(uxo, w1o, h1b);
        h2b = fmaf(uxo, w1o, h2b);
    }
    float h1 = h1a + h1b, h2 = h2a + h2b;
    float t1 = fmaxf(h1, 0.f) * av[lane];
    float t2 = fmaxf(h2, 0.f) * av[lane];
#pragma unroll
    for (int o = 16; o; o >>= 1) {
        t1 += __shfl_xor_sync(0xffffffffu, t1, o);
        t2 += __shfl_xor_sync(0xffffffffu, t2, o);
    }
    float m = fmaxf(t1, t2);
    float e1 = expf(t1 - m), e2 = expf(t2 - m);
    float inv = 1.f / (e1 + e2);
    float yc = (e1 * inv) * c1v;
    float yu = (e2 * inv) * c2v;

    out[262144 + idx] = yc + yu;
    out[524288 + idx] = yc;
    out[786432 + idx] = yu;
}

// ---------------- launch ----------------
extern "C" void kernel_launch(void* const* d_in, const int* in_sizes, int n_in,
                              void* d_out, int out_size) {
    const float* X_U      = (const float*)d_in[0];
    const float* X_C      = (const float*)d_in[1];
    const float* adj_uu   = (const float*)d_in[2];
    const float* adj_uc   = (const float*)d_in[3];
    const float* adj_cc   = (const float*)d_in[4];
    const float* weight_s = (const float*)d_in[5];
    const float* proj_u   = (const float*)d_in[6];
    const float* weight_c = (const float*)d_in[8];
    const float* W_lin    = (const float*)d_in[9];
    const float* a_vec    = (const float*)d_in[10];
    float* out = (float*)d_out;

    cudaFuncSetAttribute(k_tc, cudaFuncAttributeMaxDynamicSharedMemorySize, 3 * STAGE);

    k_sums<<<2560, 256>>>(adj_uu, adj_cc, adj_uc);
    k_dc1<<<256, 256>>>(proj_u, weight_c);
    k_build_b<<<dim3(256, 3), 256>>>(X_U, X_C, weight_s);
    k_tc<<<384, 128, 3 * STAGE>>>(adj_uu, adj_cc, adj_uc);
    k_fin<<<1024, 256>>>(X_C, W_lin, a_vec, out);
}

// round 17
// speedup vs baseline: 1.0425x; 1.0311x over previous
#include <cuda_runtime.h>
#include <cstdint>

#define NU 8192
#define NC 8192
#define NK 8192
#define D  32

// ---------------- scratch ----------------
__device__ float4 g_Bt[3 * 256 * 512];       // fragment-order B tiles (bh0,bh1,bl0,bl1), 8KB per (mat,ktile)
__device__ float g_part[2 * 3 * 8192 * 32];  // k-split(2) partials: plane = ksp*3+mat
__device__ float g_dinv_uu[NU];
__device__ float g_dinv_cc[NC];
__device__ float g_du[NU];
__device__ float g_colpart[512 * NC];        // 16 MB: per-block colsum partials (16 rows/block)

// ---------------- helpers ----------------
__device__ __forceinline__ uint32_t smem_u32(const void* p) {
    uint32_t a;
    asm("{ .reg .u64 t; cvta.to.shared.u64 t, %1; cvt.u32.u64 %0, t; }" : "=r"(a) : "l"(p));
    return a;
}
__device__ __forceinline__ void cp16(uint32_t dst, const void* src) {
    asm volatile("cp.async.cg.shared.global [%0], [%1], 16;" :: "r"(dst), "l"(src));
}
#define CP_COMMIT() asm volatile("cp.async.commit_group;" ::: "memory")
#define CP_WAIT1()  asm volatile("cp.async.wait_group 1;" ::: "memory")

__device__ __forceinline__ uint32_t tf32_rna(float x) {
    uint32_t r;
    asm("cvt.rna.tf32.f32 %0, %1;" : "=r"(r) : "f"(x));
    return r;
}
__device__ __forceinline__ float uif(uint32_t x) { return __uint_as_float(x); }

__device__ __forceinline__ void mma8(float* c, uint32_t a0, uint32_t a1,
                                     uint32_t a2, uint32_t a3,
                                     uint32_t b0, uint32_t b1) {
    asm volatile(
        "mma.sync.aligned.m16n8k8.row.col.f32.tf32.tf32.f32 "
        "{%0,%1,%2,%3}, {%4,%5,%6,%7}, {%8,%9}, {%0,%1,%2,%3};"
        : "+f"(c[0]), "+f"(c[1]), "+f"(c[2]), "+f"(c[3])
        : "r"(a0), "r"(a1), "r"(a2), "r"(a3), "r"(b0), "r"(b1));
}

__device__ __forceinline__ void ldsm4(uint32_t& r0, uint32_t& r1, uint32_t& r2,
                                      uint32_t& r3, uint32_t addr) {
    asm volatile("ldmatrix.sync.aligned.m8n8.x4.shared.b16 {%0,%1,%2,%3}, [%4];"
        : "=r"(r0), "=r"(r1), "=r"(r2), "=r"(r3) : "r"(addr));
}

// ---------------- fused pass-1 (heavy uc blocks scheduled FIRST) ----------------
// blocks [0,512):     adj_uc 16 rows/block: rowsums -> g_du, colsum partials -> g_colpart
// blocks [512,1536):  adj_uu rowsums (warp-per-row) -> g_dinv_uu
// blocks [1536,2560): adj_cc rowsums -> g_dinv_cc
__global__ void k_sums(const float* __restrict__ adj_uu,
                       const float* __restrict__ adj_cc,
                       const float* __restrict__ adj_uc) {
    int b = blockIdx.x;
    int tid = threadIdx.x;
    int w = tid >> 5, lane = tid & 31;

    if (b >= 512) {
        int bb = b - 512;
        const float* A = (bb < 1024) ? adj_uu : adj_cc;
        float* out = (bb < 1024) ? g_dinv_uu : g_dinv_cc;
        int row = ((bb < 1024) ? bb : (bb - 1024)) * 8 + w;
        const float4* p = (const float4*)(A + (size_t)row * NK) + lane;
        float s0 = 0.f, s1 = 0.f, s2 = 0.f, s3 = 0.f;
#pragma unroll 8
        for (int i = 0; i < 64; i++) {
            float4 v = p[(size_t)i * 32];
            s0 += v.x; s1 += v.y; s2 += v.z; s3 += v.w;
        }
        float s = (s0 + s1) + (s2 + s3);
#pragma unroll
        for (int o = 16; o; o >>= 1) s += __shfl_xor_sync(0xffffffffu, s, o);
        if (lane == 0) out[row] = rsqrtf(1.0f + s);
    } else {
        int ub = b;                   // 0..511
        int m0 = ub * 16;
        __shared__ float sm[16 * 8];  // [row][warp] partial rowsums
        float4 colacc[8];
#pragma unroll
        for (int i = 0; i < 8; i++) colacc[i] = make_float4(0.f, 0.f, 0.f, 0.f);

#pragma unroll 1
        for (int r = 0; r < 16; r++) {
            const float4* p = (const float4*)(adj_uc + (size_t)(m0 + r) * NK);
            float rs = 0.f;
#pragma unroll
            for (int i = 0; i < 8; i++) {
                float4 v = p[tid + i * 256];
                colacc[i].x += v.x; colacc[i].y += v.y;
                colacc[i].z += v.z; colacc[i].w += v.w;
                rs += (v.x + v.y) + (v.z + v.w);
            }
#pragma unroll
            for (int o = 16; o; o >>= 1) rs += __shfl_xor_sync(0xffffffffu, rs, o);
            if (lane == 0) sm[r * 8 + w] = rs;
        }
        __syncthreads();
        if (tid < 16) {
            float t = 0.f;
#pragma unroll
            for (int i = 0; i < 8; i++) t += sm[tid * 8 + i];
            g_du[m0 + tid] = rsqrtf(t);  // no +1 in gcn_c
        }
        float4* cp = (float4*)(g_colpart + (size_t)ub * NC);
#pragma unroll
        for (int i = 0; i < 8; i++) cp[tid + i * 256] = colacc[i];
    }
}

// ---------------- build B tiles in mma-fragment order (hi/lo split) ----------------
// mat-2 blocks: reduce their 32 dc values directly from the 512-plane g_colpart,
// and compute W2 = proj_u @ weight_c into smem (dc kernels eliminated).
__global__ void k_build_b(const float* __restrict__ X_U,
                          const float* __restrict__ X_C,
                          const float* __restrict__ weight_s,
                          const float* __restrict__ proj_u,
                          const float* __restrict__ weight_c) {
    __shared__ __align__(16) float Ws[1024];
    __shared__ float Xs[1024];
    __shared__ float sup[32 * 33];
    __shared__ float tmp[256];
    __shared__ float dcs[32];
    int mat = blockIdx.y;
    int ktile = blockIdx.x;
    int tid = threadIdx.x;  // 256

    if (mat == 2) {
        // W2 into smem (proj_u/weight_c are 4KB each, L2-resident)
#pragma unroll
        for (int e = tid; e < 1024; e += 256) {
            int i = e >> 5, j = e & 31;
            float s = 0.f;
#pragma unroll
            for (int k = 0; k < 32; k++) s += proj_u[i * 32 + k] * weight_c[k * 32 + j];
            Ws[e] = s;
        }
        // colsum reduce for this ktile's 32 columns: thread = (col, plane-group of 64)
        int col = tid & 31, grp = tid >> 5;
        const float* cp = g_colpart + (size_t)ktile * 32 + col;
        float a0 = 0.f, a1 = 0.f, a2 = 0.f, a3 = 0.f;
#pragma unroll 4
        for (int p = grp * 64; p < grp * 64 + 64; p += 4) {
            a0 += cp[(size_t)(p + 0) * NC];
            a1 += cp[(size_t)(p + 1) * NC];
            a2 += cp[(size_t)(p + 2) * NC];
            a3 += cp[(size_t)(p + 3) * NC];
        }
        tmp[tid] = (a0 + a1) + (a2 + a3);
    } else {
#pragma unroll
        for (int e = tid; e < 1024; e += 256) Ws[e] = weight_s[e];
    }
    const float* X = (mat == 1) ? X_C : X_U;
#pragma unroll
    for (int e = tid; e < 1024; e += 256) Xs[e] = X[(size_t)ktile * 1024 + e];
    __syncthreads();
    if (mat == 2 && tid < 32) {
        float t = 0.f;
#pragma unroll
        for (int i = 0; i < 8; i++) t += tmp[i * 32 + tid];
        dcs[tid] = rsqrtf(t);
    }
    __syncthreads();

    {
        int k = tid >> 3;
        int nq = (tid & 7) * 4;
        float scale;
        int gk = ktile * 32 + k;
        if (mat == 0)      scale = g_dinv_uu[gk];
        else if (mat == 1) scale = g_dinv_cc[gk];
        else               scale = dcs[k];
        float s0 = 0.f, s1 = 0.f, s2 = 0.f, s3 = 0.f;
#pragma unroll
        for (int j = 0; j < 32; j++) {
            float xj = Xs[k * 32 + j];
            float4 wv = *(const float4*)(Ws + j * 32 + nq);
            s0 = fmaf(xj, wv.x, s0);
            s1 = fmaf(xj, wv.y, s1);
            s2 = fmaf(xj, wv.z, s2);
            s3 = fmaf(xj, wv.w, s3);
        }
        sup[k * 33 + nq + 0] = scale * s0;
        sup[k * 33 + nq + 1] = scale * s1;
        sup[k * 33 + nq + 2] = scale * s2;
        sup[k * 33 + nq + 3] = scale * s3;
    }
    __syncthreads();

    float4* dst = g_Bt + ((size_t)mat * 256 + ktile) * 512;
#pragma unroll
    for (int it = 0; it < 2; it++) {
        int e = tid + it * 256;
        int lane = e & 31, nt = (e >> 5) & 3, ks = e >> 7;
        int la = lane & 3, gr = lane >> 2;
        int k0 = ks * 8 + la, n = nt * 8 + gr;
        float b0 = sup[k0 * 33 + n];
        float b1 = sup[(k0 + 4) * 33 + n];
        float h0 = uif(tf32_rna(b0));
        float h1 = uif(tf32_rna(b1));
        dst[e] = make_float4(h0, h1, b0 - h0, b1 - h1);
    }
}

// ---------------- tensor-core 2-term TF32 SpMM with ldmatrix A path ----------------
// grid 384: mat = x>>7, mb = (x&127)>>1, ksp = x&1. 128 thr, warp = m32.
// Stage (24KB) = [A 128x32 f32, 16B-unit XOR swizzle unit16=r*8+(q^(r&7)) | B 8KB fragment order].
// 3 stages, one cp.async group per chunk, wait_group 1 => 2 chunks in flight.
#define NCH2 128
#define STAGE 24576
__global__ void __launch_bounds__(128) k_tc(
    const float* __restrict__ adj_uu, const float* __restrict__ adj_cc,
    const float* __restrict__ adj_uc) {
    extern __shared__ char smem[];
    uint32_t sb = smem_u32(smem);

    int tid = threadIdx.x, wid = tid >> 5, lane = tid & 31;
    int mat = blockIdx.x >> 7;
    int rem = blockIdx.x & 127;
    int mb = rem >> 1, ksp = rem & 1;
    int m0 = mb * 128;
    int kbase = ksp * NCH2;

    const float* A = (mat == 0) ? adj_uu : (mat == 1) ? adj_cc : adj_uc;
    const float4* Bg = g_Bt + ((size_t)mat * 256 + kbase) * 512;
    const float* Ag = A + (size_t)m0 * NK + (size_t)kbase * 32;

    // cp.async map for A: e = i*128 + tid -> r = e>>3 (0..127), q = e&7 (16B block)
    const float* asrc[8];
    uint32_t adst[8];
#pragma unroll
    for (int i = 0; i < 8; i++) {
        int e = i * 128 + tid;
        int r = e >> 3, q = e & 7;
        asrc[i] = Ag + (size_t)r * NK + q * 4;
        adst[i] = (uint32_t)((r * 8 + (q ^ (r & 7))) * 16);
    }
    uint32_t bdst = (uint32_t)(16384 + tid * 16);
    const char* bsrc = (const char*)Bg + tid * 16;

    // ldmatrix per-thread offsets for (mt, ks): matrix id m = lane>>3
    uint32_t offA[8];
    {
        int m = lane >> 3;
#pragma unroll
        for (int mt = 0; mt < 2; mt++) {
#pragma unroll
            for (int ks = 0; ks < 4; ks++) {
                int r = wid * 32 + mt * 16 + (m & 1) * 8 + (lane & 7);
                int q = ks * 2 + (m >> 1);
                offA[mt * 4 + ks] = (uint32_t)((r * 8 + (q ^ (r & 7))) * 16);
            }
        }
    }

    // prologue: issue chunks 0, 1
#pragma unroll
    for (int pc = 0; pc < 2; pc++) {
        uint32_t sa = sb + (uint32_t)pc * STAGE;
#pragma unroll
        for (int i = 0; i < 8; i++) cp16(sa + adst[i], asrc[i] + pc * 32);
#pragma unroll
        for (int j = 0; j < 4; j++)
            cp16(sa + bdst + (uint32_t)j * 2048, bsrc + (size_t)pc * 8192 + j * 2048);
        CP_COMMIT();
    }

    float acc[32];
#pragma unroll
    for (int i = 0; i < 32; i++) acc[i] = 0.f;

    int s = 0, s2 = 2;  // stage of chunk t, stage of chunk t+2
    for (int t = 0; t < NCH2; t++) {
        CP_WAIT1();
        __syncthreads();

        // issue chunk t+2 into the stage freed at iter t-1
        if (t + 2 < NCH2) {
            uint32_t sa = sb + (uint32_t)s2 * STAGE;
#pragma unroll
            for (int i = 0; i < 8; i++) cp16(sa + adst[i], asrc[i] + (t + 2) * 32);
#pragma unroll
            for (int j = 0; j < 4; j++)
                cp16(sa + bdst + (uint32_t)j * 2048, bsrc + (size_t)(t + 2) * 8192 + j * 2048);
        }
        CP_COMMIT();  // always commit so wait_group counting holds through the tail

        uint32_t abase = sb + (uint32_t)s * STAGE;
        const char* stc = smem + s * STAGE + 16384;
#pragma unroll
        for (int ks = 0; ks < 4; ks++) {
            uint32_t ah[8];
#pragma unroll
            for (int mt = 0; mt < 2; mt++) {
                uint32_t r0, r1, r2, r3;
                ldsm4(r0, r1, r2, r3, abase + offA[mt * 4 + ks]);
                ah[mt * 4 + 0] = tf32_rna(uif(r0));
                ah[mt * 4 + 1] = tf32_rna(uif(r1));
                ah[mt * 4 + 2] = tf32_rna(uif(r2));
                ah[mt * 4 + 3] = tf32_rna(uif(r3));
            }
#pragma unroll
            for (int nt = 0; nt < 4; nt++) {
                float4 b = *(const float4*)(stc + ((ks * 4 + nt) * 32 + lane) * 16);
                uint32_t bh0 = __float_as_uint(b.x);
                uint32_t bh1 = __float_as_uint(b.y);
                uint32_t bl0 = __float_as_uint(b.z);
                uint32_t bl1 = __float_as_uint(b.w);
#pragma unroll
                for (int mt = 0; mt < 2; mt++) {
                    float* c = acc + mt * 16 + nt * 4;
                    mma8(c, ah[mt * 4 + 0], ah[mt * 4 + 1], ah[mt * 4 + 2], ah[mt * 4 + 3], bh0, bh1);
                    mma8(c, ah[mt * 4 + 0], ah[mt * 4 + 1], ah[mt * 4 + 2], ah[mt * 4 + 3], bl0, bl1);
                }
            }
        }
        if (++s == 3) s = 0;
        if (++s2 == 3) s2 = 0;
    }

    // partial (unscaled) store: plane = ksp*3 + mat
    float* P = g_part + ((size_t)ksp * 3 + mat) * (8192 * 32);
    int rA = m0 + wid * 32 + (lane >> 2);
#pragma unroll
    for (int mt = 0; mt < 2; mt++) {
        int row0 = rA + mt * 16;
        int row1 = row0 + 8;
#pragma unroll
        for (int nt = 0; nt < 4; nt++) {
            float* c = acc + mt * 16 + nt * 4;
            int col = nt * 8 + 2 * (lane & 3);
            *(float2*)(P + (size_t)row0 * 32 + col) = make_float2(c[0], c[1]);
            *(float2*)(P + (size_t)row1 * 32 + col) = make_float2(c[2], c[3]);
        }
    }
}

// ---------------- fused: combine partials + row scale + attention + outputs ----------------
__global__ void k_fin(const float* __restrict__ X_C,
                      const float* __restrict__ W_lin,
                      const float* __restrict__ a_vec,
                      float* __restrict__ out) {
    __shared__ float Ws[64 * 32];
    __shared__ float av[32];
    int tid = threadIdx.x;  // 256
    for (int i = tid; i < 2048; i += 256) Ws[i] = W_lin[i];
    if (tid < 32) av[tid] = a_vec[tid];
    __syncthreads();

    int lane = tid & 31;
    int row = blockIdx.x * 8 + (tid >> 5);
    size_t idx = (size_t)row * 32 + lane;

    const size_t PL = 262144;
    float pu = g_part[idx] + g_part[3 * PL + idx];
    out[idx] = g_dinv_uu[row] * pu;

    float c1v = g_dinv_cc[row] * (g_part[1 * PL + idx] + g_part[4 * PL + idx]);
    float c2v = g_du[row] * (g_part[2 * PL + idx] + g_part[5 * PL + idx]);
    float xcv = X_C[idx];

    float h1a = 0.f, h1b = 0.f, h2a = 0.f, h2b = 0.f;
#pragma unroll
    for (int k = 0; k < 32; k += 2) {
        float u1 = __shfl_sync(0xffffffffu, c1v, k);
        float u2 = __shfl_sync(0xffffffffu, c2v, k);
        float u1o = __shfl_sync(0xffffffffu, c1v, k + 1);
        float u2o = __shfl_sync(0xffffffffu, c2v, k + 1);
        float w0 = Ws[k * 32 + lane];
        float w0o = Ws[(k + 1) * 32 + lane];
        h1a = fmaf(u1, w0, h1a);
        h2a = fmaf(u2, w0, h2a);
        h1b = fmaf(u1o, w0o, h1b);
        h2b = fmaf(u2o, w0o, h2b);
    }
#pragma unroll
    for (int k = 0; k < 32; k += 2) {
        float ux = __shfl_sync(0xffffffffu, xcv, k);
        float uxo = __shfl_sync(0xffffffffu, xcv, k + 1);
        float w1 = Ws[(32 + k) * 32 + lane];
        float w1o = Ws[(33 + k) * 32 + lane];
        h1a = fmaf(ux, w1, h1a);
        h2a = fmaf(ux, w1, h2a);
        h1b = fmaf(uxo, w1o, h1b);
        h2b = fmaf(uxo, w1o, h2b);
    }
    float h1 = h1a + h1b, h2 = h2a + h2b;
    float t1 = fmaxf(h1, 0.f) * av[lane];
    float t2 = fmaxf(h2, 0.f) * av[lane];
#pragma unroll
    for (int o = 16; o; o >>= 1) {
        t1 += __shfl_xor_sync(0xffffffffu, t1, o);
        t2 += __shfl_xor_sync(0xffffffffu, t2, o);
    }
    float m = fmaxf(t1, t2);
    float e1 = expf(t1 - m), e2 = expf(t2 - m);
    float inv = 1.f / (e1 + e2);
    float yc = (e1 * inv) * c1v;
    float yu = (e2 * inv) * c2v;

    out[262144 + idx] = yc + yu;
    out[524288 + idx] = yc;
    out[786432 + idx] = yu;
}

// ---------------- launch ----------------
extern "C" void kernel_launch(void* const* d_in, const int* in_sizes, int n_in,
                              void* d_out, int out_size) {
    const float* X_U      = (const float*)d_in[0];
    const float* X_C      = (const float*)d_in[1];
    const float* adj_uu   = (const float*)d_in[2];
    const float* adj_uc   = (const float*)d_in[3];
    const float* adj_cc   = (const float*)d_in[4];
    const float* weight_s = (const float*)d_in[5];
    const float* proj_u   = (const float*)d_in[6];
    const float* weight_c = (const float*)d_in[8];
    const float* W_lin    = (const float*)d_in[9];
    const float* a_vec    = (const float*)d_in[10];
    float* out = (float*)d_out;

    cudaFuncSetAttribute(k_tc, cudaFuncAttributeMaxDynamicSharedMemorySize, 3 * STAGE);

    k_sums<<<2560, 256>>>(adj_uu, adj_cc, adj_uc);
    k_build_b<<<dim3(256, 3), 256>>>(X_U, X_C, weight_s, proj_u, weight_c);
    k_tc<<<384, 128, 3 * STAGE>>>(adj_uu, adj_cc, adj_uc);
    k_fin<<<1024, 256>>>(X_C, W_lin, a_vec, out);
}